// round 1
// baseline (speedup 1.0000x reference)
#include <cuda_runtime.h>

// Problem geometry: N = (262144, 65536, 16384), R_final = 21
#define NI 16384               // n_min = N[2]
#define A_ELEMS (21 * 21 * NI) // 7225344 per plane
#define LOGDET_IDX (2 * A_ELEMS)
#define ZOUT_OFF (LOGDET_IDX + 1)
#define ZOUT_PLANE (21 * NI)
#define K1_BLOCKS 128

struct Cpx { float re, im; };

__device__ __forceinline__ Cpx cmul(Cpx a, Cpx b) {
    Cpx r; r.re = a.re * b.re - a.im * b.im; r.im = a.re * b.im + a.im * b.re; return r;
}
// a * conj(b)
__device__ __forceinline__ Cpx cmulc(Cpx a, Cpx b) {
    Cpx r; r.re = a.re * b.re + a.im * b.im; r.im = a.im * b.re - a.re * b.im; return r;
}
__device__ __forceinline__ Cpx cinv(Cpx a) {
    float d = 1.0f / (a.re * a.re + a.im * a.im);
    Cpx r; r.re = a.re * d; r.im = -a.im * d; return r;
}

// Scratch (device globals — allocation-free). ~2.7 MB, stays in L2 between kernels.
__device__ float g_T2_re[20 * NI];
__device__ float g_T2_im[20 * NI];
__device__ float g_invS2_re[NI];
__device__ float g_invS2_im[NI];
__device__ double g_ld_partial[K1_BLOCKS];

// ---------------------------------------------------------------------------
// Kernel 1: per final frequency i, compute T2 (20 complex), invS2, logdet partials.
// ---------------------------------------------------------------------------
__global__ void __launch_bounds__(128) k1(
    const float* __restrict__ l00r, const float* __restrict__ l00i,
    const float* __restrict__ l01r, const float* __restrict__ l01i,
    const float* __restrict__ l02r, const float* __restrict__ l02i,
    const float* __restrict__ l11r, const float* __restrict__ l11i,
    const float* __restrict__ l12r, const float* __restrict__ l12i,
    const float* __restrict__ l22r, const float* __restrict__ l22i)
{
    const int i = blockIdx.x * 128 + threadIdx.x;
    double acc = 0.0;
    Cpx M2; M2.re = 0.f; M2.im = 0.f;

    #pragma unroll
    for (int s = 0; s < 4; s++) {
        const int m = s * NI + i;
        Cpx a0[4], T1[4];
        Cpx M1; M1.re = 0.f; M1.im = 0.f;
        #pragma unroll
        for (int jj = 0; jj < 4; jj++) {
            const int idx = (jj * 4 + s) * NI + i;
            Cpx l00; l00.re = l00r[idx]; l00.im = l00i[idx];
            Cpx l01; l01.re = l01r[idx]; l01.im = l01i[idx];
            a0[jj] = cinv(l00);
            T1[jj] = cmul(l01, a0[jj]);
            Cpx t = cmulc(T1[jj], l01);        // conj(l01) * T1
            M1.re += t.re; M1.im += t.im;
            acc += 0.5 * (double)logf(l00.re * l00.re + l00.im * l00.im);
        }
        Cpx S1; S1.re = l11r[m] - M1.re; S1.im = l11i[m] - M1.im;
        acc += 0.5 * (double)logf(S1.re * S1.re + S1.im * S1.im);
        const Cpx invS1 = cinv(S1);

        Cpx b[5];
        #pragma unroll
        for (int p = 0; p < 4; p++) {
            const int idx = (p * 4 + s) * NI + i;
            b[p].re = l02r[idx]; b[p].im = l02i[idx];
        }
        b[4].re = l12r[m]; b[4].im = l12i[m];

        // w = sum_{p<4} conj(T1[p]) * b[p]
        Cpx w; w.re = 0.f; w.im = 0.f;
        #pragma unroll
        for (int p = 0; p < 4; p++) {
            Cpx t = cmulc(b[p], T1[p]);
            w.re += t.re; w.im += t.im;
        }
        Cpx wm; wm.re = w.re - b[4].re; wm.im = w.im - b[4].im;

        // Row 4 accumulator: invS1*b4 - sum conj(P1[p]) b[p]
        Cpx t2b = cmul(invS1, b[4]);

        #pragma unroll
        for (int q = 0; q < 4; q++) {
            const Cpx P1q = cmul(T1[q], invS1);
            // T2[q*4+s] = P1[q]*(w - b4) + a0[q]*b[q]
            Cpx t2 = cmul(P1q, wm);
            Cpx t = cmul(a0[q], b[q]);
            t2.re += t.re; t2.im += t.im;
            const int k = q * 4 + s;
            g_T2_re[k * NI + i] = t2.re;
            g_T2_im[k * NI + i] = t2.im;
            Cpx mm = cmulc(t2, b[q]);          // conj(b)*T2
            M2.re += mm.re; M2.im += mm.im;
            Cpx u = cmulc(b[q], P1q);          // conj(P1)*b
            t2b.re -= u.re; t2b.im -= u.im;
        }
        g_T2_re[(16 + s) * NI + i] = t2b.re;
        g_T2_im[(16 + s) * NI + i] = t2b.im;
        Cpx mm = cmulc(t2b, b[4]);
        M2.re += mm.re; M2.im += mm.im;
    }

    Cpx S2; S2.re = l22r[i] - M2.re; S2.im = l22i[i] - M2.im;
    acc += 0.5 * (double)logf(S2.re * S2.re + S2.im * S2.im);
    const Cpx invS2 = cinv(S2);
    g_invS2_re[i] = invS2.re;
    g_invS2_im[i] = invS2.im;

    // Deterministic block reduction (shuffle tree + shared), partial per block.
    __shared__ double sh[4];
    #pragma unroll
    for (int off = 16; off > 0; off >>= 1)
        acc += __shfl_down_sync(0xffffffffu, acc, off);
    const int lane = threadIdx.x & 31, warp = threadIdx.x >> 5;
    if (lane == 0) sh[warp] = acc;
    __syncthreads();
    if (threadIdx.x == 0)
        g_ld_partial[blockIdx.x] = sh[0] + sh[1] + sh[2] + sh[3];
}

// ---------------------------------------------------------------------------
// Kernel 2: one thread per (i, output row j). Writes row j of A and zout[j,i].
// ---------------------------------------------------------------------------
__global__ void __launch_bounds__(128) k2(
    const float* __restrict__ l00r, const float* __restrict__ l00i,
    const float* __restrict__ l01r, const float* __restrict__ l01i,
    const float* __restrict__ l11r, const float* __restrict__ l11i,
    const float* __restrict__ zre,  const float* __restrict__ zim,
    float* __restrict__ out)
{
    const int i = blockIdx.x * 128 + threadIdx.x;
    const int j = blockIdx.y;

    if (j == 0 && blockIdx.x == 0 && threadIdx.x == 0) {
        double t = 0.0;
        #pragma unroll 8
        for (int b = 0; b < K1_BLOCKS; b++) t += g_ld_partial[b];
        out[LOGDET_IDX] = (float)t;
    }

    Cpx invS2; invS2.re = g_invS2_re[i]; invS2.im = g_invS2_im[i];
    Cpx zacc; zacc.re = 0.f; zacc.im = 0.f;

    float* outAre = out + (size_t)j * 21 * NI + i;
    float* outAim = out + A_ELEMS + (size_t)j * 21 * NI + i;

    if (j < 20) {
        const int s = j & 3, p = j >> 2;
        // Recompute level-1 quantities for this s (loads hit L2; cheaper than staging A1).
        Cpx a0[4], T1[4];
        Cpx M1; M1.re = 0.f; M1.im = 0.f;
        #pragma unroll
        for (int jj = 0; jj < 4; jj++) {
            const int idx = (jj * 4 + s) * NI + i;
            Cpx l00; l00.re = l00r[idx]; l00.im = l00i[idx];
            Cpx l01; l01.re = l01r[idx]; l01.im = l01i[idx];
            a0[jj] = cinv(l00);
            T1[jj] = cmul(l01, a0[jj]);
            Cpx t = cmulc(T1[jj], l01);
            M1.re += t.re; M1.im += t.im;
        }
        const int m = s * NI + i;
        Cpx S1; S1.re = l11r[m] - M1.re; S1.im = l11i[m] - M1.im;
        const Cpx invS1 = cinv(S1);

        Cpx A1row[5];  // A1_s[p][q], q = 0..4
        if (p < 4) {
            const Cpx P1p = cmul(T1[p], invS1);
            #pragma unroll
            for (int q = 0; q < 4; q++) A1row[q] = cmulc(P1p, T1[q]);
            A1row[p].re += a0[p].re; A1row[p].im += a0[p].im;
            A1row[4].re = -P1p.re; A1row[4].im = -P1p.im;
        } else {
            #pragma unroll
            for (int q = 0; q < 4; q++) {
                Cpx P1q = cmul(T1[q], invS1);
                A1row[q].re = -P1q.re; A1row[q].im = P1q.im;   // -conj(P1[q])
            }
            A1row[4] = invS1;
        }

        Cpx T2j; T2j.re = g_T2_re[j * NI + i]; T2j.im = g_T2_im[j * NI + i];
        const Cpx P2j = cmul(T2j, invS2);

        #pragma unroll
        for (int k = 0; k < 20; k++) {
            Cpx T2k; T2k.re = g_T2_re[k * NI + i]; T2k.im = g_T2_im[k * NI + i];
            Cpx val = cmulc(P2j, T2k);                 // P2[j] * conj(T2[k])
            if ((k & 3) == s) {                        // scatter of A1
                val.re += A1row[k >> 2].re; val.im += A1row[k >> 2].im;
            }
            outAre[k * NI] = val.re; outAim[k * NI] = val.im;
            Cpx zk; zk.re = zre[k * NI + i]; zk.im = zim[k * NI + i];
            Cpx t = cmul(zk, val);
            zacc.re += t.re; zacc.im += t.im;
        }
        // k = 20: A[j,20] = -P2[j]
        Cpx val; val.re = -P2j.re; val.im = -P2j.im;
        outAre[20 * NI] = val.re; outAim[20 * NI] = val.im;
        Cpx z20; z20.re = zre[20 * NI + i]; z20.im = zim[20 * NI + i];
        Cpx t = cmul(z20, val);
        zacc.re += t.re; zacc.im += t.im;
    } else {
        // Row 20: A[20,k] = -conj(P2[k]),  A[20,20] = 1/S2
        #pragma unroll
        for (int k = 0; k < 20; k++) {
            Cpx T2k; T2k.re = g_T2_re[k * NI + i]; T2k.im = g_T2_im[k * NI + i];
            Cpx P2k = cmul(T2k, invS2);
            Cpx val; val.re = -P2k.re; val.im = P2k.im;
            outAre[k * NI] = val.re; outAim[k * NI] = val.im;
            Cpx zk; zk.re = zre[k * NI + i]; zk.im = zim[k * NI + i];
            Cpx t = cmul(zk, val);
            zacc.re += t.re; zacc.im += t.im;
        }
        outAre[20 * NI] = invS2.re; outAim[20 * NI] = invS2.im;
        Cpx z20; z20.re = zre[20 * NI + i]; z20.im = zim[20 * NI + i];
        Cpx t = cmul(z20, invS2);
        zacc.re += t.re; zacc.im += t.im;
    }

    out[ZOUT_OFF + j * NI + i] = zacc.re;
    out[ZOUT_OFF + ZOUT_PLANE + j * NI + i] = zacc.im;
}

extern "C" void kernel_launch(void* const* d_in, const int* in_sizes, int n_in,
                              void* d_out, int out_size)
{
    const float* l00r = (const float*)d_in[0];
    const float* l00i = (const float*)d_in[1];
    const float* l01r = (const float*)d_in[2];
    const float* l01i = (const float*)d_in[3];
    const float* l02r = (const float*)d_in[4];
    const float* l02i = (const float*)d_in[5];
    const float* l11r = (const float*)d_in[6];
    const float* l11i = (const float*)d_in[7];
    const float* l12r = (const float*)d_in[8];
    const float* l12i = (const float*)d_in[9];
    const float* l22r = (const float*)d_in[10];
    const float* l22i = (const float*)d_in[11];
    const float* zre  = (const float*)d_in[12];
    const float* zim  = (const float*)d_in[13];
    float* out = (float*)d_out;

    k1<<<K1_BLOCKS, 128>>>(l00r, l00i, l01r, l01i, l02r, l02i,
                           l11r, l11i, l12r, l12i, l22r, l22i);
    dim3 g2(NI / 128, 21);
    k2<<<g2, 128>>>(l00r, l00i, l01r, l01i, l11r, l11i, zre, zim, out);
}

// round 3
// speedup vs baseline: 1.5317x; 1.5317x over previous
#include <cuda_runtime.h>

// Problem geometry: N = (262144, 65536, 16384), final block rank R = 21
#define NI 16384               // n_min = N[2]
#define A_ELEMS (21 * 21 * NI)
#define LOGDET_IDX (2 * A_ELEMS)
#define ZOUT_OFF (LOGDET_IDX + 1)
#define ZOUT_PLANE (21 * NI)
#define TILE_I 32
#define NBLK (NI / TILE_I)     // 512 blocks
#define NTHREADS (21 * TILE_I) // 672

struct Cpx { float re, im; };

__device__ __forceinline__ Cpx cmul(Cpx a, Cpx b) {
    Cpx r; r.re = a.re * b.re - a.im * b.im; r.im = a.re * b.im + a.im * b.re; return r;
}
// a * conj(b)
__device__ __forceinline__ Cpx cmulc(Cpx a, Cpx b) {
    Cpx r; r.re = a.re * b.re + a.im * b.im; r.im = a.im * b.re - a.re * b.im; return r;
}
__device__ __forceinline__ Cpx cinv(Cpx a) {
    float d = 1.0f / (a.re * a.re + a.im * a.im);
    Cpx r; r.re = a.re * d; r.im = -a.im * d; return r;
}

__device__ double g_ld[NBLK];   // per-block logdet partials

// ---------------------------------------------------------------------------
// Fused kernel: per 32-i tile, compute everything in shared, write A + zout.
// Warp j (0..20) owns output row j; lane = i within tile.
// ---------------------------------------------------------------------------
__global__ void __launch_bounds__(NTHREADS, 2) kmain(
    const float* __restrict__ l00r, const float* __restrict__ l00i,
    const float* __restrict__ l01r, const float* __restrict__ l01i,
    const float* __restrict__ l02r, const float* __restrict__ l02i,
    const float* __restrict__ l11r, const float* __restrict__ l11i,
    const float* __restrict__ l12r, const float* __restrict__ l12i,
    const float* __restrict__ l22r, const float* __restrict__ l22i,
    const float* __restrict__ zre,  const float* __restrict__ zim,
    float* __restrict__ out)
{
    __shared__ float2 shT2[20][TILE_I];       // level-2 T vector
    __shared__ float2 shA1[4][25][TILE_I];    // per-s 5x5 level-1 inverse
    __shared__ float  shZre[21][TILE_I];
    __shared__ float  shZim[21][TILE_I];
    __shared__ float2 shM2[4][TILE_I];
    __shared__ float2 shInvS2[TILE_I];
    __shared__ double shLdW[5];

    const int lane = threadIdx.x & 31;
    const int warp = threadIdx.x >> 5;
    const int i = blockIdx.x * TILE_I + lane;

    double acc = 0.0;

    // ---- Phase 1: warps 0..3 compute level-1 + T2/M2/A1 for s = warp ----
    if (warp < 4) {
        const int s = warp;
        const int m = s * NI + i;
        Cpx a0[4], T1[4];
        Cpx M1; M1.re = 0.f; M1.im = 0.f;
        #pragma unroll
        for (int jj = 0; jj < 4; jj++) {
            const int idx = (jj * 4 + s) * NI + i;
            Cpx l00; l00.re = l00r[idx]; l00.im = l00i[idx];
            Cpx l01; l01.re = l01r[idx]; l01.im = l01i[idx];
            a0[jj] = cinv(l00);
            T1[jj] = cmul(l01, a0[jj]);
            Cpx t = cmulc(T1[jj], l01);
            M1.re += t.re; M1.im += t.im;
            acc += 0.5 * (double)logf(l00.re * l00.re + l00.im * l00.im);
        }
        Cpx S1; S1.re = l11r[m] - M1.re; S1.im = l11i[m] - M1.im;
        acc += 0.5 * (double)logf(S1.re * S1.re + S1.im * S1.im);
        const Cpx invS1 = cinv(S1);

        Cpx b[5];
        #pragma unroll
        for (int p = 0; p < 4; p++) {
            const int idx = (p * 4 + s) * NI + i;
            b[p].re = l02r[idx]; b[p].im = l02i[idx];
        }
        b[4].re = l12r[m]; b[4].im = l12i[m];

        // w = sum_p conj(T1[p]) * b[p]
        Cpx w; w.re = 0.f; w.im = 0.f;
        #pragma unroll
        for (int p = 0; p < 4; p++) {
            Cpx t = cmulc(b[p], T1[p]);
            w.re += t.re; w.im += t.im;
        }
        Cpx wm; wm.re = w.re - b[4].re; wm.im = w.im - b[4].im;

        Cpx t2b = cmul(invS1, b[4]);
        Cpx M2; M2.re = 0.f; M2.im = 0.f;
        Cpx P1[4];
        #pragma unroll
        for (int q = 0; q < 4; q++) {
            P1[q] = cmul(T1[q], invS1);
            Cpx t2 = cmul(P1[q], wm);
            Cpx t = cmul(a0[q], b[q]);
            t2.re += t.re; t2.im += t.im;
            shT2[q * 4 + s][lane] = make_float2(t2.re, t2.im);
            Cpx mm = cmulc(t2, b[q]);
            M2.re += mm.re; M2.im += mm.im;
            Cpx u = cmulc(b[q], P1[q]);
            t2b.re -= u.re; t2b.im -= u.im;
        }
        shT2[16 + s][lane] = make_float2(t2b.re, t2b.im);
        Cpx mm = cmulc(t2b, b[4]);
        M2.re += mm.re; M2.im += mm.im;
        shM2[s][lane] = make_float2(M2.re, M2.im);

        // A1 (5x5) for this s
        #pragma unroll
        for (int p = 0; p < 4; p++) {
            #pragma unroll
            for (int q = 0; q < 4; q++) {
                Cpx v = cmulc(P1[p], T1[q]);
                if (q == p) { v.re += a0[p].re; v.im += a0[p].im; }
                shA1[s][p * 5 + q][lane] = make_float2(v.re, v.im);
            }
            shA1[s][p * 5 + 4][lane] = make_float2(-P1[p].re, -P1[p].im);
        }
        #pragma unroll
        for (int q = 0; q < 4; q++)
            shA1[s][20 + q][lane] = make_float2(-P1[q].re, P1[q].im);   // -conj(P1)
        shA1[s][24][lane] = make_float2(invS1.re, invS1.im);
    }

    // ---- z staging: warp j loads its own plane (coalesced 128B) ----
    shZre[warp][lane] = zre[warp * NI + i];
    shZim[warp][lane] = zim[warp * NI + i];

    __syncthreads();

    // ---- Phase 1b: warp 4 computes S2 / invS2 / log|S2| ----
    if (warp == 4) {
        float2 m0 = shM2[0][lane], m1 = shM2[1][lane],
               m2 = shM2[2][lane], m3 = shM2[3][lane];
        Cpx S2; S2.re = l22r[i] - (m0.x + m1.x + m2.x + m3.x);
                S2.im = l22i[i] - (m0.y + m1.y + m2.y + m3.y);
        acc = 0.5 * (double)logf(S2.re * S2.re + S2.im * S2.im);
        Cpx inv = cinv(S2);
        shInvS2[lane] = make_float2(inv.re, inv.im);
    }

    // ---- logdet: deterministic in-block reduction (warps 0..4) ----
    if (warp < 5) {
        #pragma unroll
        for (int off = 16; off > 0; off >>= 1)
            acc += __shfl_down_sync(0xffffffffu, acc, off);
        if (lane == 0) shLdW[warp] = acc;
    }
    __syncthreads();
    if (threadIdx.x == 0)
        g_ld[blockIdx.x] = shLdW[0] + shLdW[1] + shLdW[2] + shLdW[3] + shLdW[4];

    // ---- Phase 2: warp j writes row j of A (both planes) + zout[j] ----
    const int j = warp;
    float2 vinv = shInvS2[lane];
    Cpx invS2; invS2.re = vinv.x; invS2.im = vinv.y;

    float* outAre = out + (size_t)j * 21 * NI + i;
    float* outAim = out + A_ELEMS + (size_t)j * 21 * NI + i;
    Cpx zacc; zacc.re = 0.f; zacc.im = 0.f;

    if (j < 20) {
        const int s = j & 3, p = j >> 2;
        float2 t2j = shT2[j][lane];
        Cpx T2j; T2j.re = t2j.x; T2j.im = t2j.y;
        const Cpx P2j = cmul(T2j, invS2);

        #pragma unroll
        for (int k = 0; k < 20; k++) {
            float2 tk = shT2[k][lane];
            Cpx T2k; T2k.re = tk.x; T2k.im = tk.y;
            Cpx val = cmulc(P2j, T2k);
            if ((k & 3) == s) {
                float2 a = shA1[s][p * 5 + (k >> 2)][lane];
                val.re += a.x; val.im += a.y;
            }
            __stcs(outAre + k * NI, val.re);
            __stcs(outAim + k * NI, val.im);
            Cpx zk; zk.re = shZre[k][lane]; zk.im = shZim[k][lane];
            Cpx t = cmul(zk, val);
            zacc.re += t.re; zacc.im += t.im;
        }
        Cpx val; val.re = -P2j.re; val.im = -P2j.im;   // col 20: -P2[j]
        __stcs(outAre + 20 * NI, val.re);
        __stcs(outAim + 20 * NI, val.im);
        Cpx z20; z20.re = shZre[20][lane]; z20.im = shZim[20][lane];
        Cpx t = cmul(z20, val);
        zacc.re += t.re; zacc.im += t.im;
    } else {
        // Row 20: -conj(P2[k]) ... 1/S2
        #pragma unroll
        for (int k = 0; k < 20; k++) {
            float2 tk = shT2[k][lane];
            Cpx T2k; T2k.re = tk.x; T2k.im = tk.y;
            Cpx P2k = cmul(T2k, invS2);
            Cpx val; val.re = -P2k.re; val.im = P2k.im;
            __stcs(outAre + k * NI, val.re);
            __stcs(outAim + k * NI, val.im);
            Cpx zk; zk.re = shZre[k][lane]; zk.im = shZim[k][lane];
            Cpx t = cmul(zk, val);
            zacc.re += t.re; zacc.im += t.im;
        }
        __stcs(outAre + 20 * NI, invS2.re);
        __stcs(outAim + 20 * NI, invS2.im);
        Cpx z20; z20.re = shZre[20][lane]; z20.im = shZim[20][lane];
        Cpx t = cmul(z20, invS2);
        zacc.re += t.re; zacc.im += t.im;
    }

    __stcs(out + ZOUT_OFF + j * NI + i, zacc.re);
    __stcs(out + ZOUT_OFF + ZOUT_PLANE + j * NI + i, zacc.im);
}

// ---------------------------------------------------------------------------
// Tiny deterministic logdet fold: 512 partials -> scalar.
// ---------------------------------------------------------------------------
__global__ void __launch_bounds__(128) kreduce(float* __restrict__ out)
{
    __shared__ double sh[128];
    const int t = threadIdx.x;
    double a = g_ld[t] + g_ld[t + 128] + g_ld[t + 256] + g_ld[t + 384];
    sh[t] = a;
    __syncthreads();
    #pragma unroll
    for (int off = 64; off > 0; off >>= 1) {
        if (t < off) sh[t] += sh[t + off];
        __syncthreads();
    }
    if (t == 0) out[LOGDET_IDX] = (float)sh[0];
}

extern "C" void kernel_launch(void* const* d_in, const int* in_sizes, int n_in,
                              void* d_out, int out_size)
{
    const float* l00r = (const float*)d_in[0];
    const float* l00i = (const float*)d_in[1];
    const float* l01r = (const float*)d_in[2];
    const float* l01i = (const float*)d_in[3];
    const float* l02r = (const float*)d_in[4];
    const float* l02i = (const float*)d_in[5];
    const float* l11r = (const float*)d_in[6];
    const float* l11i = (const float*)d_in[7];
    const float* l12r = (const float*)d_in[8];
    const float* l12i = (const float*)d_in[9];
    const float* l22r = (const float*)d_in[10];
    const float* l22i = (const float*)d_in[11];
    const float* zre  = (const float*)d_in[12];
    const float* zim  = (const float*)d_in[13];
    float* out = (float*)d_out;

    kmain<<<NBLK, NTHREADS>>>(l00r, l00i, l01r, l01i, l02r, l02i,
                              l11r, l11i, l12r, l12i, l22r, l22i,
                              zre, zim, out);
    kreduce<<<1, 128>>>(out);
}

// round 6
// speedup vs baseline: 1.7294x; 1.1291x over previous
#include <cuda_runtime.h>

// Problem geometry: N = (262144, 65536, 16384), final block rank R = 21
#define NI 16384               // n_min = N[2]
#define A_ELEMS (21 * 21 * NI)
#define LOGDET_IDX (2 * A_ELEMS)
#define ZOUT_OFF (LOGDET_IDX + 1)   // NOTE: odd float offset -> scalar stores only!
#define ZOUT_PLANE (21 * NI)
#define TILE_I 64
#define NBLK (NI / TILE_I)     // 256 blocks
#define NTHREADS (21 * 32)     // 672

// Dynamic shared layout (float2 units)
#define SM_T2    0
#define SM_A1    (20 * 64)
#define SM_Z     (SM_A1 + 100 * 64)
#define SM_M2    (SM_Z + 21 * 64)
#define SM_INVS2 (SM_M2 + 4 * 64)
#define SM_F2_COUNT (SM_INVS2 + 64)          // 9344 float2 = 74752 B
#define SMEM_BYTES (SM_F2_COUNT * 8 + 128)   // + logdet scratch

struct Cpx { float re, im; };

__device__ __forceinline__ Cpx cmul(Cpx a, Cpx b) {
    Cpx r; r.re = a.re * b.re - a.im * b.im; r.im = a.re * b.im + a.im * b.re; return r;
}
// a * conj(b)
__device__ __forceinline__ Cpx cmulc(Cpx a, Cpx b) {
    Cpx r; r.re = a.re * b.re + a.im * b.im; r.im = a.im * b.re - a.re * b.im; return r;
}
__device__ __forceinline__ Cpx cinv(Cpx a) {
    float d = 1.0f / (a.re * a.re + a.im * a.im);
    Cpx r; r.re = a.re * d; r.im = -a.im * d; return r;
}

__device__ double g_ld[NBLK];
__device__ unsigned int g_count = 0;

__global__ void __launch_bounds__(NTHREADS, 2) kmain(
    const float* __restrict__ l00r, const float* __restrict__ l00i,
    const float* __restrict__ l01r, const float* __restrict__ l01i,
    const float* __restrict__ l02r, const float* __restrict__ l02i,
    const float* __restrict__ l11r, const float* __restrict__ l11i,
    const float* __restrict__ l12r, const float* __restrict__ l12i,
    const float* __restrict__ l22r, const float* __restrict__ l22i,
    const float* __restrict__ zre,  const float* __restrict__ zim,
    float* __restrict__ out)
{
    extern __shared__ float2 sm[];
    float2* shT2    = sm + SM_T2;
    float2* shA1    = sm + SM_A1;
    float2* shZ     = sm + SM_Z;
    float2* shM2    = sm + SM_M2;
    float2* shInvS2 = sm + SM_INVS2;
    double* shLd    = (double*)(sm + SM_F2_COUNT);
    int*    shLast  = (int*)(shLd + 10);

    const int lane = threadIdx.x & 31;
    const int warp = threadIdx.x >> 5;
    const int base = blockIdx.x * TILE_I;

    double acc = 0.0;

    // ---- Phase 1: warps 0..7 handle (s = warp&3, half = warp>>2) ----
    if (warp < 8) {
        const int s = warp & 3, half = warp >> 2;
        const int ii = half * 32 + lane;
        const int i = base + ii;
        const int m = s * NI + i;

        Cpx a0[4], T1[4];
        Cpx M1; M1.re = 0.f; M1.im = 0.f;
        #pragma unroll
        for (int jj = 0; jj < 4; jj++) {
            const int idx = (jj * 4 + s) * NI + i;
            Cpx l00; l00.re = l00r[idx]; l00.im = l00i[idx];
            Cpx l01; l01.re = l01r[idx]; l01.im = l01i[idx];
            a0[jj] = cinv(l00);
            T1[jj] = cmul(l01, a0[jj]);
            Cpx t = cmulc(T1[jj], l01);
            M1.re += t.re; M1.im += t.im;
            acc += 0.5 * (double)logf(l00.re * l00.re + l00.im * l00.im);
        }
        Cpx S1; S1.re = l11r[m] - M1.re; S1.im = l11i[m] - M1.im;
        acc += 0.5 * (double)logf(S1.re * S1.re + S1.im * S1.im);
        const Cpx invS1 = cinv(S1);

        Cpx b[5];
        #pragma unroll
        for (int p = 0; p < 4; p++) {
            const int idx = (p * 4 + s) * NI + i;
            b[p].re = l02r[idx]; b[p].im = l02i[idx];
        }
        b[4].re = l12r[m]; b[4].im = l12i[m];

        Cpx w; w.re = 0.f; w.im = 0.f;
        #pragma unroll
        for (int p = 0; p < 4; p++) {
            Cpx t = cmulc(b[p], T1[p]);
            w.re += t.re; w.im += t.im;
        }
        Cpx wm; wm.re = w.re - b[4].re; wm.im = w.im - b[4].im;

        Cpx t2b = cmul(invS1, b[4]);
        Cpx M2; M2.re = 0.f; M2.im = 0.f;
        Cpx P1[4];
        #pragma unroll
        for (int q = 0; q < 4; q++) {
            P1[q] = cmul(T1[q], invS1);
            Cpx t2 = cmul(P1[q], wm);
            Cpx t = cmul(a0[q], b[q]);
            t2.re += t.re; t2.im += t.im;
            shT2[(q * 4 + s) * 64 + ii] = make_float2(t2.re, t2.im);
            Cpx mm = cmulc(t2, b[q]);
            M2.re += mm.re; M2.im += mm.im;
            Cpx u = cmulc(b[q], P1[q]);
            t2b.re -= u.re; t2b.im -= u.im;
        }
        shT2[(16 + s) * 64 + ii] = make_float2(t2b.re, t2b.im);
        Cpx mm = cmulc(t2b, b[4]);
        M2.re += mm.re; M2.im += mm.im;
        shM2[s * 64 + ii] = make_float2(M2.re, M2.im);

        // A1 (5x5) for this s
        #pragma unroll
        for (int p = 0; p < 4; p++) {
            #pragma unroll
            for (int q = 0; q < 4; q++) {
                Cpx v = cmulc(P1[p], T1[q]);
                if (q == p) { v.re += a0[p].re; v.im += a0[p].im; }
                shA1[(s * 25 + p * 5 + q) * 64 + ii] = make_float2(v.re, v.im);
            }
            shA1[(s * 25 + p * 5 + 4) * 64 + ii] = make_float2(-P1[p].re, -P1[p].im);
        }
        #pragma unroll
        for (int q = 0; q < 4; q++)
            shA1[(s * 25 + 20 + q) * 64 + ii] = make_float2(-P1[q].re, P1[q].im);
        shA1[(s * 25 + 24) * 64 + ii] = make_float2(invS1.re, invS1.im);
    }

    // ---- z staging: warp j loads its plane's 64 re + 64 im via float2 ----
    {
        const float2* zr2 = (const float2*)(zre + warp * NI + base);
        const float2* zi2 = (const float2*)(zim + warp * NI + base);
        float2 r = zr2[lane];
        float2 im = zi2[lane];
        shZ[warp * 64 + 2 * lane]     = make_float2(r.x, im.x);
        shZ[warp * 64 + 2 * lane + 1] = make_float2(r.y, im.y);
    }

    __syncthreads();

    // ---- Phase 1b: warps 8,9 compute S2 / invS2 / log|S2| ----
    if (warp == 8 || warp == 9) {
        const int ii = (warp - 8) * 32 + lane;
        const int i = base + ii;
        float2 m0 = shM2[0 * 64 + ii], m1 = shM2[1 * 64 + ii],
               m2 = shM2[2 * 64 + ii], m3 = shM2[3 * 64 + ii];
        Cpx S2; S2.re = l22r[i] - (m0.x + m1.x + m2.x + m3.x);
                S2.im = l22i[i] - (m0.y + m1.y + m2.y + m3.y);
        acc = 0.5 * (double)logf(S2.re * S2.re + S2.im * S2.im);
        Cpx inv = cinv(S2);
        shInvS2[ii] = make_float2(inv.re, inv.im);
    }

    // ---- per-block logdet partial (warps 0..9) ----
    if (warp < 10) {
        #pragma unroll
        for (int off = 16; off > 0; off >>= 1)
            acc += __shfl_down_sync(0xffffffffu, acc, off);
        if (lane == 0) shLd[warp] = acc;
    }
    __syncthreads();
    if (threadIdx.x == 0) {
        double p = 0.0;
        #pragma unroll
        for (int w = 0; w < 10; w++) p += shLd[w];
        g_ld[blockIdx.x] = p;
        __threadfence();
        unsigned int v = atomicAdd(&g_count, 1u);
        *shLast = (v == NBLK - 1) ? 1 : 0;
    }
    __syncthreads();
    const int isLast = *shLast;

    // ---- Phase 2: warp j writes row j of A (both planes, 2 i per thread) ----
    const int j = warp;
    const int i0 = base + 2 * lane;
    float4 vi = *(const float4*)(shInvS2 + 2 * lane);
    Cpx is0; is0.re = vi.x; is0.im = vi.y;
    Cpx is1; is1.re = vi.z; is1.im = vi.w;

    float* outAre = out + (size_t)j * 21 * NI + i0;
    float* outAim = out + A_ELEMS + (size_t)j * 21 * NI + i0;
    Cpx za0, za1;
    za0.re = za0.im = za1.re = za1.im = 0.f;

    Cpx P2j0, P2j1;
    if (j < 20) {
        float4 t2 = *(const float4*)(shT2 + j * 64 + 2 * lane);
        Cpx T0; T0.re = t2.x; T0.im = t2.y;
        Cpx T1c; T1c.re = t2.z; T1c.im = t2.w;
        P2j0 = cmul(T0, is0);
        P2j1 = cmul(T1c, is1);
        const int s = j & 3, p = j >> 2;

        #pragma unroll
        for (int k = 0; k < 20; k++) {
            float4 tk = *(const float4*)(shT2 + k * 64 + 2 * lane);
            Cpx Tk0; Tk0.re = tk.x; Tk0.im = tk.y;
            Cpx Tk1; Tk1.re = tk.z; Tk1.im = tk.w;
            Cpx v0 = cmulc(P2j0, Tk0);
            Cpx v1 = cmulc(P2j1, Tk1);
            if ((k & 3) == s) {
                float4 a = *(const float4*)(shA1 + (s * 25 + p * 5 + (k >> 2)) * 64 + 2 * lane);
                v0.re += a.x; v0.im += a.y;
                v1.re += a.z; v1.im += a.w;
            }
            __stcs((float2*)(outAre + (size_t)k * NI), make_float2(v0.re, v1.re));
            __stcs((float2*)(outAim + (size_t)k * NI), make_float2(v0.im, v1.im));
            float4 zk = *(const float4*)(shZ + k * 64 + 2 * lane);
            Cpx z0; z0.re = zk.x; z0.im = zk.y;
            Cpx z1; z1.re = zk.z; z1.im = zk.w;
            Cpx t0 = cmul(z0, v0); za0.re += t0.re; za0.im += t0.im;
            Cpx t1 = cmul(z1, v1); za1.re += t1.re; za1.im += t1.im;
        }
        // col 20: -P2[j]
        Cpx v0; v0.re = -P2j0.re; v0.im = -P2j0.im;
        Cpx v1; v1.re = -P2j1.re; v1.im = -P2j1.im;
        __stcs((float2*)(outAre + (size_t)20 * NI), make_float2(v0.re, v1.re));
        __stcs((float2*)(outAim + (size_t)20 * NI), make_float2(v0.im, v1.im));
        float4 zk = *(const float4*)(shZ + 20 * 64 + 2 * lane);
        Cpx z0; z0.re = zk.x; z0.im = zk.y;
        Cpx z1; z1.re = zk.z; z1.im = zk.w;
        Cpx t0 = cmul(z0, v0); za0.re += t0.re; za0.im += t0.im;
        Cpx t1 = cmul(z1, v1); za1.re += t1.re; za1.im += t1.im;
    } else {
        // Row 20: -conj(P2[k]) ... 1/S2
        #pragma unroll
        for (int k = 0; k < 20; k++) {
            float4 tk = *(const float4*)(shT2 + k * 64 + 2 * lane);
            Cpx Tk0; Tk0.re = tk.x; Tk0.im = tk.y;
            Cpx Tk1; Tk1.re = tk.z; Tk1.im = tk.w;
            Cpx P0 = cmul(Tk0, is0);
            Cpx P1c = cmul(Tk1, is1);
            Cpx v0; v0.re = -P0.re; v0.im = P0.im;
            Cpx v1; v1.re = -P1c.re; v1.im = P1c.im;
            __stcs((float2*)(outAre + (size_t)k * NI), make_float2(v0.re, v1.re));
            __stcs((float2*)(outAim + (size_t)k * NI), make_float2(v0.im, v1.im));
            float4 zk = *(const float4*)(shZ + k * 64 + 2 * lane);
            Cpx z0; z0.re = zk.x; z0.im = zk.y;
            Cpx z1; z1.re = zk.z; z1.im = zk.w;
            Cpx t0 = cmul(z0, v0); za0.re += t0.re; za0.im += t0.im;
            Cpx t1 = cmul(z1, v1); za1.re += t1.re; za1.im += t1.im;
        }
        __stcs((float2*)(outAre + (size_t)20 * NI), make_float2(is0.re, is1.re));
        __stcs((float2*)(outAim + (size_t)20 * NI), make_float2(is0.im, is1.im));
        float4 zk = *(const float4*)(shZ + 20 * 64 + 2 * lane);
        Cpx z0; z0.re = zk.x; z0.im = zk.y;
        Cpx z1; z1.re = zk.z; z1.im = zk.w;
        Cpx t0 = cmul(z0, is0); za0.re += t0.re; za0.im += t0.im;
        Cpx t1 = cmul(z1, is1); za1.re += t1.re; za1.im += t1.im;
    }

    // zout base offset is ODD (LOGDET scalar precedes it) -> scalar stores.
    {
        float* zoR = out + ZOUT_OFF + (size_t)j * NI + i0;
        float* zoI = out + ZOUT_OFF + ZOUT_PLANE + (size_t)j * NI + i0;
        __stcs(zoR,     za0.re);
        __stcs(zoR + 1, za1.re);
        __stcs(zoI,     za0.im);
        __stcs(zoI + 1, za1.im);
    }

    // ---- last block finalizes logdet (deterministic fixed-order sum) ----
    if (isLast && warp == 0) {
        double a = 0.0;
        #pragma unroll
        for (int q = 0; q < NBLK / 32; q++)
            a += g_ld[q * 32 + lane];
        #pragma unroll
        for (int off = 16; off > 0; off >>= 1)
            a += __shfl_xor_sync(0xffffffffu, a, off);
        if (lane == 0) {
            out[LOGDET_IDX] = (float)a;
            g_count = 0;   // reset for next launch / graph replay
        }
    }
}

extern "C" void kernel_launch(void* const* d_in, const int* in_sizes, int n_in,
                              void* d_out, int out_size)
{
    const float* l00r = (const float*)d_in[0];
    const float* l00i = (const float*)d_in[1];
    const float* l01r = (const float*)d_in[2];
    const float* l01i = (const float*)d_in[3];
    const float* l02r = (const float*)d_in[4];
    const float* l02i = (const float*)d_in[5];
    const float* l11r = (const float*)d_in[6];
    const float* l11i = (const float*)d_in[7];
    const float* l12r = (const float*)d_in[8];
    const float* l12i = (const float*)d_in[9];
    const float* l22r = (const float*)d_in[10];
    const float* l22i = (const float*)d_in[11];
    const float* zre  = (const float*)d_in[12];
    const float* zim  = (const float*)d_in[13];
    float* out = (float*)d_out;

    static int smem_set = 0;
    if (!smem_set) {
        cudaFuncSetAttribute(kmain, cudaFuncAttributeMaxDynamicSharedMemorySize, SMEM_BYTES);
        smem_set = 1;
    }
    kmain<<<NBLK, NTHREADS, SMEM_BYTES>>>(l00r, l00i, l01r, l01i, l02r, l02i,
                                          l11r, l11i, l12r, l12i, l22r, l22i,
                                          zre, zim, out);
}